// round 1
// baseline (speedup 1.0000x reference)
#include <cuda_runtime.h>
#include <cuda_bf16.h>
#include <math.h>

// Problem constants
#define BATCH 64
#define QQ 900
#define TT 256
#define LL 769
#define MM (BATCH * QQ)      // 57600
#define KSEL 50
#define CAP 16384
#define NSAMP 2048
#define SAMP_STRIDE 337      // 337*2048 = 690176 <= 692100
#define RANK_SEL 8           // take 8th largest sample as threshold

// GEMM tiling
#define BM 128
#define BN 64
#define BK 16
#define NTHREADS 256

// ---------------- static scratch (no allocations allowed) ----------------
__device__ float              g_sig[MM * TT];                 // 59 MB sigmoid(logits)
__device__ float              g_thr[BATCH];
__device__ int                g_cnt[BATCH];
__device__ unsigned long long g_cand[BATCH * CAP];           // 8 MB packed candidates

__constant__ int TOKEN_IDXS_C[80] = {
    0, 9, 19, 25, 38, 49, 55, 63, 71, 78, 94, 109, 121, 137, 145, 152, 158,
    164, 172, 180, 186, 197, 204, 212, 222, 233, 244, 254, 260, 271, 281, 288,
    300, 314, 321, 336, 353, 366, 378, 394, 403, 416, 422, 429, 437, 445, 452,
    461, 469, 480, 489, 500, 509, 519, 527, 535, 542, 550, 558, 573, 579, 594,
    603, 608, 617, 625, 634, 645, 658, 670, 677, 687, 694, 709, 716, 724, 731,
    742, 755, 768};

// ---------------- packed f32x2 helpers (Blackwell) ----------------
__device__ __forceinline__ unsigned long long fma2(unsigned long long a,
                                                   unsigned long long b,
                                                   unsigned long long c) {
    unsigned long long d;
    asm("fma.rn.f32x2 %0, %1, %2, %3;" : "=l"(d) : "l"(a), "l"(b), "l"(c));
    return d;
}
__device__ __forceinline__ unsigned long long dup2(float x) {
    unsigned int u = __float_as_uint(x);
    return ((unsigned long long)u << 32) | (unsigned long long)u;
}

// ---------------- K1: sigmoid ----------------
__global__ void k_sigmoid(const float* __restrict__ logits) {
    int n4 = MM * TT / 4;
    const float4* in = (const float4*)logits;
    float4* out = (float4*)g_sig;
    for (int i = blockIdx.x * blockDim.x + threadIdx.x; i < n4;
         i += gridDim.x * blockDim.x) {
        float4 v = in[i];
        v.x = 1.f / (1.f + expf(-v.x));
        v.y = 1.f / (1.f + expf(-v.y));
        v.z = 1.f / (1.f + expf(-v.z));
        v.w = 1.f / (1.f + expf(-v.w));
        out[i] = v;
    }
}

// ---------------- K2: per-batch sampled threshold (and counter reset) ------
__global__ void k_threshold(const float* __restrict__ pos_map) {
    int b = blockIdx.x;
    int tid = threadIdx.x;
    int warp = tid >> 5, lane = tid & 31;
    __shared__ float samp[NSAMP];
    __shared__ float red[NTHREADS];

    if (tid == 0) g_cnt[b] = 0;

    // warp-cooperative sampled dot products
    for (int i = warp; i < NSAMP; i += 8) {
        int s = i * SAMP_STRIDE;
        int q = s / LL;
        int l = s - q * LL;
        const float4* arow =
            (const float4*)(g_sig + ((size_t)(b * QQ + q)) * TT);
        const float4* brow = (const float4*)(pos_map + (size_t)l * TT);
        float4 a0 = arow[lane * 2], a1 = arow[lane * 2 + 1];
        float4 b0 = brow[lane * 2], b1 = brow[lane * 2 + 1];
        float sum = a0.x * b0.x + a0.y * b0.y + a0.z * b0.z + a0.w * b0.w +
                    a1.x * b1.x + a1.y * b1.y + a1.z * b1.z + a1.w * b1.w;
        #pragma unroll
        for (int off = 16; off > 0; off >>= 1)
            sum += __shfl_down_sync(0xFFFFFFFFu, sum, off);
        if (lane == 0) samp[i] = sum;
    }
    __syncthreads();

    // find RANK_SEL-th largest sample via iterated strict-max
    float prev = 3.4e38f;
    for (int it = 0; it < RANK_SEL; ++it) {
        float best = -3.4e38f;
        for (int i = tid; i < NSAMP; i += NTHREADS) {
            float v = samp[i];
            if (v < prev && v > best) best = v;
        }
        red[tid] = best;
        __syncthreads();
        for (int s = NTHREADS / 2; s > 0; s >>= 1) {
            if (tid < s && red[tid + s] > red[tid]) red[tid] = red[tid + s];
            __syncthreads();
        }
        prev = red[0];
        __syncthreads();
    }
    if (tid == 0) g_thr[b] = prev;
}

// ---------------- K3: fused GEMM (f32x2) + threshold filter ----------------
__global__ void __launch_bounds__(NTHREADS)
k_gemm_filter(const float* __restrict__ pos_map) {
    __shared__ unsigned long long Asd[BK][BM];  // duplicated-halves A, 16 KB
    __shared__ float Bs[BK][BN];                // 4 KB

    int tid = threadIdx.x;
    int m0 = blockIdx.y * BM;
    int n0 = blockIdx.x * BN;

    // load-index precompute
    int arow0 = tid >> 2;            // 0..63
    int ak4   = (tid & 3) * 4;       // k sub-offset
    int brow  = tid >> 2;            // 0..63
    int bk4   = (tid & 3) * 4;
    int lB    = n0 + brow;

    const float* Ag = g_sig + (size_t)m0 * TT;
    const float* Bg = pos_map;

    int tx = tid & 15;   // n group: cols tx*4..tx*4+3
    int ty = tid >> 4;   // m group: rows ty*8..ty*8+7

    unsigned long long acc[8][2];
    #pragma unroll
    for (int i = 0; i < 8; ++i) { acc[i][0] = 0ull; acc[i][1] = 0ull; }

    // prefetch chunk 0
    float4 a0r, a1r, b0r;
    {
        a0r = *(const float4*)(Ag + (size_t)arow0 * TT + ak4);
        a1r = *(const float4*)(Ag + (size_t)(arow0 + 64) * TT + ak4);
        if (lB < LL) b0r = *(const float4*)(Bg + (size_t)lB * TT + bk4);
        else         b0r = make_float4(0.f, 0.f, 0.f, 0.f);
    }

    const int NCHUNK = TT / BK;  // 16
    for (int kc = 0; kc < NCHUNK; ++kc) {
        __syncthreads();
        // store prefetched regs to smem (A duplicated into both f32x2 halves)
        {
            const float* ap0 = &a0r.x;
            const float* ap1 = &a1r.x;
            const float* bp  = &b0r.x;
            #pragma unroll
            for (int j = 0; j < 4; ++j) {
                Asd[ak4 + j][arow0]      = dup2(ap0[j]);
                Asd[ak4 + j][arow0 + 64] = dup2(ap1[j]);
                Bs[bk4 + j][brow]        = bp[j];
            }
        }
        __syncthreads();

        // prefetch next chunk
        if (kc + 1 < NCHUNK) {
            int ko = (kc + 1) * BK;
            a0r = *(const float4*)(Ag + (size_t)arow0 * TT + ko + ak4);
            a1r = *(const float4*)(Ag + (size_t)(arow0 + 64) * TT + ko + ak4);
            if (lB < LL) b0r = *(const float4*)(Bg + (size_t)lB * TT + ko + bk4);
        }

        // compute
        #pragma unroll
        for (int k = 0; k < BK; ++k) {
            ulonglong2 bb = *(ulonglong2*)&Bs[k][tx * 4];
            ulonglong2 pa01 = *(ulonglong2*)&Asd[k][ty * 8 + 0];
            ulonglong2 pa23 = *(ulonglong2*)&Asd[k][ty * 8 + 2];
            ulonglong2 pa45 = *(ulonglong2*)&Asd[k][ty * 8 + 4];
            ulonglong2 pa67 = *(ulonglong2*)&Asd[k][ty * 8 + 6];
            acc[0][0] = fma2(pa01.x, bb.x, acc[0][0]);
            acc[0][1] = fma2(pa01.x, bb.y, acc[0][1]);
            acc[1][0] = fma2(pa01.y, bb.x, acc[1][0]);
            acc[1][1] = fma2(pa01.y, bb.y, acc[1][1]);
            acc[2][0] = fma2(pa23.x, bb.x, acc[2][0]);
            acc[2][1] = fma2(pa23.x, bb.y, acc[2][1]);
            acc[3][0] = fma2(pa23.y, bb.x, acc[3][0]);
            acc[3][1] = fma2(pa23.y, bb.y, acc[3][1]);
            acc[4][0] = fma2(pa45.x, bb.x, acc[4][0]);
            acc[4][1] = fma2(pa45.x, bb.y, acc[4][1]);
            acc[5][0] = fma2(pa45.y, bb.x, acc[5][0]);
            acc[5][1] = fma2(pa45.y, bb.y, acc[5][1]);
            acc[6][0] = fma2(pa67.x, bb.x, acc[6][0]);
            acc[6][1] = fma2(pa67.x, bb.y, acc[6][1]);
            acc[7][0] = fma2(pa67.y, bb.x, acc[7][0]);
            acc[7][1] = fma2(pa67.y, bb.y, acc[7][1]);
        }
    }

    // epilogue: filter + append packed keys
    int lbase = n0 + tx * 4;
    #pragma unroll
    for (int i = 0; i < 8; ++i) {
        int m = m0 + ty * 8 + i;
        int b = m / QQ;
        int q = m - b * QQ;
        float thrv = g_thr[b];
        #pragma unroll
        for (int j = 0; j < 2; ++j) {
            float lo = __uint_as_float((unsigned)(acc[i][j] & 0xFFFFFFFFull));
            float hi = __uint_as_float((unsigned)(acc[i][j] >> 32));
            int l0 = lbase + 2 * j;
            if (l0 < LL && lo >= thrv) {
                unsigned lin = (unsigned)(q * LL + l0);
                unsigned long long key =
                    ((unsigned long long)__float_as_uint(lo) << 32) |
                    (unsigned long long)(0xFFFFFFFFu - lin);
                int pos = atomicAdd(&g_cnt[b], 1);
                if (pos < CAP) g_cand[(size_t)b * CAP + pos] = key;
            }
            if (l0 + 1 < LL && hi >= thrv) {
                unsigned lin = (unsigned)(q * LL + l0 + 1);
                unsigned long long key =
                    ((unsigned long long)__float_as_uint(hi) << 32) |
                    (unsigned long long)(0xFFFFFFFFu - lin);
                int pos = atomicAdd(&g_cnt[b], 1);
                if (pos < CAP) g_cand[(size_t)b * CAP + pos] = key;
            }
        }
    }
}

// ---------------- K4: per-batch final top-50 + outputs ----------------
// out layout (float32): [vals B*50 | labels B*50 | boxes B*50*4]
__global__ void k_final(const float* __restrict__ out_bbox,
                        const float* __restrict__ target_sizes,
                        float* __restrict__ out) {
    int b = blockIdx.x;
    int tid = threadIdx.x;
    __shared__ unsigned long long red[NTHREADS];
    __shared__ unsigned long long selKey;

    int n = g_cnt[b];
    if (n > CAP) n = CAP;
    const unsigned long long* cand = g_cand + (size_t)b * CAP;

    unsigned long long prev = 0xFFFFFFFFFFFFFFFFull;
    for (int j = 0; j < KSEL; ++j) {
        unsigned long long best = 0ull;
        for (int t = tid; t < n; t += NTHREADS) {
            unsigned long long k = cand[t];
            if (k < prev && k > best) best = k;
        }
        red[tid] = best;
        __syncthreads();
        for (int s = NTHREADS / 2; s > 0; s >>= 1) {
            if (tid < s && red[tid + s] > red[tid]) red[tid] = red[tid + s];
            __syncthreads();
        }
        if (tid == 0) selKey = red[0];
        __syncthreads();
        unsigned long long key = selKey;
        prev = key;
        __syncthreads();

        if (tid == 0) {
            float v = __uint_as_float((unsigned)(key >> 32));
            unsigned lin = 0xFFFFFFFFu - (unsigned)(key & 0xFFFFFFFFull);
            int q = (int)(lin / LL);
            int tok = (int)(lin - (unsigned)q * LL);
            int cls = 0;
            #pragma unroll
            for (int c = 0; c < 80; ++c)
                if (TOKEN_IDXS_C[c] == tok) cls = c;

            out[b * KSEL + j] = v;
            out[BATCH * KSEL + b * KSEL + j] = (float)cls;

            const float* bb = out_bbox + ((size_t)(b * QQ + q)) * 4;
            float cx = bb[0], cy = bb[1], w = bb[2], h = bb[3];
            float img_h = target_sizes[b * 2 + 0];
            float img_w = target_sizes[b * 2 + 1];
            float* ob = out + 2 * BATCH * KSEL + ((size_t)(b * KSEL + j)) * 4;
            ob[0] = (cx - 0.5f * w) * img_w;
            ob[1] = (cy - 0.5f * h) * img_h;
            ob[2] = (cx + 0.5f * w) * img_w;
            ob[3] = (cy + 0.5f * h) * img_h;
        }
        __syncthreads();
    }
}

extern "C" void kernel_launch(void* const* d_in, const int* in_sizes, int n_in,
                              void* d_out, int out_size) {
    const float* out_logits   = (const float*)d_in[0];
    const float* out_bbox     = (const float*)d_in[1];
    const float* pos_map      = (const float*)d_in[2];
    const float* target_sizes = (const float*)d_in[3];
    float* out = (float*)d_out;

    k_sigmoid<<<2048, NTHREADS>>>(out_logits);
    k_threshold<<<BATCH, NTHREADS>>>(pos_map);
    dim3 grid((LL + BN - 1) / BN, MM / BM);  // 13 x 450
    k_gemm_filter<<<grid, NTHREADS>>>(pos_map);
    k_final<<<BATCH, NTHREADS>>>(out_bbox, target_sizes, out);
}

// round 3
// speedup vs baseline: 1.8777x; 1.8777x over previous
#include <cuda_runtime.h>
#include <cuda_bf16.h>
#include <math.h>
#include <stdint.h>

// ---------------- problem constants ----------------
#define BATCH 64
#define QQ 900
#define TT 256
#define LL 769
#define LLPAD 896            // 7 * 128
#define MM (BATCH * QQ)      // 57600
#define KSEL 50
#define CAP 32768
#define NSAMP 1024
#define SAMP_STRIDE 675      // 675*1024 = 691200 <= 692100
#define RANK_SEL 4
#define MARGIN 0.02f
#define NTHREADS 256

// GEMM tiling
#define BM 128
#define BN 128
#define BK 32
#define PITCH 80             // bytes per 32-col bf16 row (conflict-free ldmatrix)
#define STAGE_BYTES (4 * 128 * PITCH)   // AH,AL,BH,BL each 128 rows -> 40960
#define SMEM_TOTAL (2 * STAGE_BYTES)    // 81920

// ---------------- static scratch ----------------
__device__ __align__(256) __nv_bfloat16 g_Ahi[MM * TT];
__device__ __align__(256) __nv_bfloat16 g_Alo[MM * TT];
__device__ __align__(256) __nv_bfloat16 g_Bhi[LLPAD * TT];
__device__ __align__(256) __nv_bfloat16 g_Blo[LLPAD * TT];
__device__ float              g_thr[BATCH];
__device__ int                g_cnt[BATCH * 32];              // 128B stride/batch
__device__ unsigned long long g_cand[BATCH * CAP];            // 16 MB

__constant__ int TOKEN_IDXS_C[80] = {
    0, 9, 19, 25, 38, 49, 55, 63, 71, 78, 94, 109, 121, 137, 145, 152, 158,
    164, 172, 180, 186, 197, 204, 212, 222, 233, 244, 254, 260, 271, 281, 288,
    300, 314, 321, 336, 353, 366, 378, 394, 403, 416, 422, 429, 437, 445, 452,
    461, 469, 480, 489, 500, 509, 519, 527, 535, 542, 550, 558, 573, 579, 594,
    603, 608, 617, 625, 634, 645, 658, 670, 677, 687, 694, 709, 716, 724, 731,
    742, 755, 768};

// ---------------- PTX helpers ----------------
__device__ __forceinline__ uint32_t smem_u32(const void* p) {
    uint32_t a;
    asm("{ .reg .u64 t; cvta.to.shared.u64 t, %1; cvt.u32.u64 %0, t; }"
        : "=r"(a) : "l"(p));
    return a;
}
__device__ __forceinline__ void cpa16(uint32_t s, const void* g) {
    asm volatile("cp.async.cg.shared.global [%0], [%1], 16;" :: "r"(s), "l"(g));
}
#define CP_COMMIT() asm volatile("cp.async.commit_group;" ::: "memory")
#define CP_WAIT1()  asm volatile("cp.async.wait_group 1;" ::: "memory")
#define CP_WAIT0()  asm volatile("cp.async.wait_group 0;" ::: "memory")

__device__ __forceinline__ void ldsm4(uint32_t& r0, uint32_t& r1, uint32_t& r2,
                                      uint32_t& r3, uint32_t addr) {
    asm volatile("ldmatrix.sync.aligned.m8n8.x4.shared.b16 {%0,%1,%2,%3}, [%4];"
                 : "=r"(r0), "=r"(r1), "=r"(r2), "=r"(r3) : "r"(addr));
}
__device__ __forceinline__ void mma16816(float* d, const uint32_t* a,
                                         uint32_t b0, uint32_t b1) {
    asm volatile(
        "mma.sync.aligned.m16n8k16.row.col.f32.bf16.bf16.f32 "
        "{%0,%1,%2,%3}, {%4,%5,%6,%7}, {%8,%9}, {%0,%1,%2,%3};"
        : "+f"(d[0]), "+f"(d[1]), "+f"(d[2]), "+f"(d[3])
        : "r"(a[0]), "r"(a[1]), "r"(a[2]), "r"(a[3]), "r"(b0), "r"(b1));
}

// ---------------- K1: sigmoid + hi/lo bf16 split (A and B) ----------------
__global__ void k_convert(const float* __restrict__ logits,
                          const float* __restrict__ pos_map) {
    int stride = gridDim.x * blockDim.x;
    int tid0 = blockIdx.x * blockDim.x + threadIdx.x;

    int n4a = MM * TT / 4;
    const float4* in = (const float4*)logits;
    for (int i = tid0; i < n4a; i += stride) {
        float4 v = in[i];
        float a0 = 1.f / (1.f + expf(-v.x));
        float a1 = 1.f / (1.f + expf(-v.y));
        float a2 = 1.f / (1.f + expf(-v.z));
        float a3 = 1.f / (1.f + expf(-v.w));
        float h0 = __bfloat162float(__float2bfloat16_rn(a0));
        float h1 = __bfloat162float(__float2bfloat16_rn(a1));
        float h2 = __bfloat162float(__float2bfloat16_rn(a2));
        float h3 = __bfloat162float(__float2bfloat16_rn(a3));
        ((__nv_bfloat162*)g_Ahi)[i * 2]     = __floats2bfloat162_rn(h0, h1);
        ((__nv_bfloat162*)g_Ahi)[i * 2 + 1] = __floats2bfloat162_rn(h2, h3);
        ((__nv_bfloat162*)g_Alo)[i * 2]     = __floats2bfloat162_rn(a0 - h0, a1 - h1);
        ((__nv_bfloat162*)g_Alo)[i * 2 + 1] = __floats2bfloat162_rn(a2 - h2, a3 - h3);
    }

    int n4b = LLPAD * TT / 4;
    const float4* pin = (const float4*)pos_map;
    for (int i = tid0; i < n4b; i += stride) {
        int l = i >> 6;   // row (64 float4 per 256-col row)
        float4 v;
        if (l < LL) v = pin[i];
        else        v = make_float4(0.f, 0.f, 0.f, 0.f);
        float h0 = __bfloat162float(__float2bfloat16_rn(v.x));
        float h1 = __bfloat162float(__float2bfloat16_rn(v.y));
        float h2 = __bfloat162float(__float2bfloat16_rn(v.z));
        float h3 = __bfloat162float(__float2bfloat16_rn(v.w));
        ((__nv_bfloat162*)g_Bhi)[i * 2]     = __floats2bfloat162_rn(h0, h1);
        ((__nv_bfloat162*)g_Bhi)[i * 2 + 1] = __floats2bfloat162_rn(h2, h3);
        ((__nv_bfloat162*)g_Blo)[i * 2]     = __floats2bfloat162_rn(v.x - h0, v.y - h1);
        ((__nv_bfloat162*)g_Blo)[i * 2 + 1] = __floats2bfloat162_rn(v.z - h2, v.w - h3);
    }
}

// ---------------- K2: per-batch sampled threshold ----------------
__global__ void k_threshold(const float* __restrict__ pos_map) {
    int b = blockIdx.x;
    int tid = threadIdx.x;
    int warp = tid >> 5, lane = tid & 31;
    __shared__ float samp[NSAMP];
    __shared__ float red[NTHREADS];

    if (tid == 0) g_cnt[b * 32] = 0;

    for (int i = warp; i < NSAMP; i += 8) {
        int s = i * SAMP_STRIDE;
        int q = s / LL;
        int l = s - q * LL;
        const __nv_bfloat162* ah =
            (const __nv_bfloat162*)(g_Ahi + (size_t)(b * QQ + q) * TT) + lane * 4;
        const __nv_bfloat162* al =
            (const __nv_bfloat162*)(g_Alo + (size_t)(b * QQ + q) * TT) + lane * 4;
        const float2* pr = (const float2*)(pos_map + (size_t)l * TT) + lane * 4;
        float sum = 0.f;
        #pragma unroll
        for (int j = 0; j < 4; ++j) {
            float2 h = __bfloat1622float2(ah[j]);
            float2 lo = __bfloat1622float2(al[j]);
            float2 p = pr[j];
            sum += (h.x + lo.x) * p.x + (h.y + lo.y) * p.y;
        }
        #pragma unroll
        for (int off = 16; off > 0; off >>= 1)
            sum += __shfl_down_sync(0xFFFFFFFFu, sum, off);
        if (lane == 0) samp[i] = sum;
    }
    __syncthreads();

    float prev = 3.4e38f;
    for (int it = 0; it < RANK_SEL; ++it) {
        float best = -3.4e38f;
        for (int i = tid; i < NSAMP; i += NTHREADS) {
            float v = samp[i];
            if (v < prev && v > best) best = v;
        }
        red[tid] = best;
        __syncthreads();
        for (int s = NTHREADS / 2; s > 0; s >>= 1) {
            if (tid < s && red[tid + s] > red[tid]) red[tid] = red[tid + s];
            __syncthreads();
        }
        prev = red[0];
        __syncthreads();
    }
    if (tid == 0) g_thr[b] = prev - MARGIN;
}

// ---------------- K3: split-bf16 HMMA GEMM + filter ----------------
// stage layout: AH @0, AL @10240, BH @20480, BL @30720 (each 128 rows * 80B)
__device__ __forceinline__ void load_stage(uint32_t sb, int s, int kc,
                                           int m0, int n0, int tid) {
    uint32_t base = sb + s * STAGE_BYTES;
    #pragma unroll
    for (int i = 0; i < 2; ++i) {
        int idx = tid + 256 * i;        // 0..511
        int row = idx >> 2;             // 0..127
        int kv = idx & 3;               // 16B vec within 64B row
        uint32_t so = (uint32_t)(row * PITCH + kv * 16);
        size_t ga = (size_t)(m0 + row) * TT + kc * BK + kv * 8;
        size_t gb = (size_t)(n0 + row) * TT + kc * BK + kv * 8;
        cpa16(base + so,         g_Ahi + ga);
        cpa16(base + 10240 + so, g_Alo + ga);
        cpa16(base + 20480 + so, g_Bhi + gb);
        cpa16(base + 30720 + so, g_Blo + gb);
    }
    CP_COMMIT();
}

__global__ void __launch_bounds__(NTHREADS, 1) k_gemm() {
    extern __shared__ char smem[];
    uint32_t sb = smem_u32(smem);
    int tid = threadIdx.x;
    int wid = tid >> 5, lane = tid & 31;
    int warp_m = wid >> 2;      // 0..1   (64 rows)
    int warp_n = wid & 3;       // 0..3   (32 cols)
    int m0 = blockIdx.y * BM;
    int n0 = blockIdx.x * BN;

    float acc[4][4][4];
    #pragma unroll
    for (int a = 0; a < 4; ++a)
        #pragma unroll
        for (int b = 0; b < 4; ++b)
            #pragma unroll
            for (int c = 0; c < 4; ++c) acc[a][b][c] = 0.f;

    // ldmatrix addressing
    int a_row = (lane & 15);
    int a_cb  = (lane >> 4) * 16;               // col-half bytes
    int b_row = (lane & 7) + ((lane >> 4) & 1) * 8;
    int b_cb  = ((lane >> 3) & 1) * 16;

    load_stage(sb, 0, 0, m0, n0, tid);

    const int NKC = TT / BK;   // 8
    for (int kc = 0; kc < NKC; ++kc) {
        int s = kc & 1;
        if (kc + 1 < NKC) {
            load_stage(sb, (kc + 1) & 1, kc + 1, m0, n0, tid);
            CP_WAIT1();
        } else {
            CP_WAIT0();
        }
        __syncthreads();

        uint32_t AH = sb + s * STAGE_BYTES;
        uint32_t AL = AH + 10240;
        uint32_t BH = AH + 20480;
        uint32_t BL = AH + 30720;

        #pragma unroll
        for (int k16 = 0; k16 < 2; ++k16) {
            uint32_t koff = (uint32_t)(k16 * 32);
            uint32_t aH[4][4], aL[4][4], bH[2][4], bL[2][4];
            #pragma unroll
            for (int mt = 0; mt < 4; ++mt) {
                uint32_t ao =
                    (uint32_t)((warp_m * 64 + mt * 16 + a_row) * PITCH) + a_cb + koff;
                ldsm4(aH[mt][0], aH[mt][1], aH[mt][2], aH[mt][3], AH + ao);
                ldsm4(aL[mt][0], aL[mt][1], aL[mt][2], aL[mt][3], AL + ao);
            }
            #pragma unroll
            for (int nt = 0; nt < 2; ++nt) {
                uint32_t bo =
                    (uint32_t)((warp_n * 32 + nt * 16 + b_row) * PITCH) + b_cb + koff;
                ldsm4(bH[nt][0], bH[nt][1], bH[nt][2], bH[nt][3], BH + bo);
                ldsm4(bL[nt][0], bL[nt][1], bL[nt][2], bL[nt][3], BL + bo);
            }
            #pragma unroll
            for (int mt = 0; mt < 4; ++mt)
                #pragma unroll
                for (int nt16 = 0; nt16 < 2; ++nt16)
                    #pragma unroll
                    for (int h = 0; h < 2; ++h) {
                        int nt = nt16 * 2 + h;
                        mma16816(acc[mt][nt], aH[mt], bH[nt16][2 * h], bH[nt16][2 * h + 1]);
                        mma16816(acc[mt][nt], aH[mt], bL[nt16][2 * h], bL[nt16][2 * h + 1]);
                        mma16816(acc[mt][nt], aL[mt], bH[nt16][2 * h], bH[nt16][2 * h + 1]);
                    }
        }
        __syncthreads();
    }

    // ---------------- epilogue: threshold filter + append ----------------
    int g = lane >> 2, tg = lane & 3;
    #pragma unroll
    for (int mt = 0; mt < 4; ++mt) {
        #pragma unroll
        for (int half = 0; half < 2; ++half) {
            int m = m0 + warp_m * 64 + mt * 16 + g + half * 8;
            int b = m / QQ;
            int q = m - b * QQ;
            float thr = g_thr[b];
            #pragma unroll
            for (int nt = 0; nt < 4; ++nt) {
                #pragma unroll
                for (int j = 0; j < 2; ++j) {
                    float v = acc[mt][nt][half * 2 + j];
                    int l = n0 + warp_n * 32 + nt * 8 + tg * 2 + j;
                    if (l < LL && v >= thr) {
                        unsigned lin = (unsigned)(q * LL + l);
                        unsigned long long key =
                            ((unsigned long long)__float_as_uint(v) << 32) |
                            (unsigned long long)(0xFFFFFFFFu - lin);
                        int pos = atomicAdd(&g_cnt[b * 32], 1);
                        if (pos < CAP) g_cand[(size_t)b * CAP + pos] = key;
                    }
                }
            }
        }
    }
}

// ---------------- K4: per-batch top-50 + outputs ----------------
__global__ void k_final(const float* __restrict__ out_bbox,
                        const float* __restrict__ target_sizes,
                        float* __restrict__ out) {
    int b = blockIdx.x;
    int tid = threadIdx.x;
    int wid = tid >> 5, lane = tid & 31;
    __shared__ unsigned long long wmax[8];

    int n = g_cnt[b * 32];
    if (n > CAP) n = CAP;
    const unsigned long long* cand = g_cand + (size_t)b * CAP;

    unsigned long long loc[KSEL];
    int cnt = 0;
    for (int t = tid; t < n; t += NTHREADS) {
        unsigned long long k = cand[t];
        if (cnt < KSEL) {
            int j = cnt++;
            while (j > 0 && loc[j - 1] < k) { loc[j] = loc[j - 1]; --j; }
            loc[j] = k;
        } else if (k > loc[KSEL - 1]) {
            int j = KSEL - 1;
            while (j > 0 && loc[j - 1] < k) { loc[j] = loc[j - 1]; --j; }
            loc[j] = k;
        }
    }

    int p = 0;
    for (int j = 0; j < KSEL; ++j) {
        unsigned long long h = (p < cnt) ? loc[p] : 0ull;
        unsigned long long v = h;
        #pragma unroll
        for (int off = 16; off > 0; off >>= 1) {
            unsigned long long o = __shfl_xor_sync(0xFFFFFFFFu, v, off);
            if (o > v) v = o;
        }
        if (lane == 0) wmax[wid] = v;
        __syncthreads();
        if (tid == 0) {
            unsigned long long m = wmax[0];
            #pragma unroll
            for (int w = 1; w < 8; ++w) if (wmax[w] > m) m = wmax[w];
            wmax[0] = m;
        }
        __syncthreads();
        unsigned long long best = wmax[0];
        if (h != 0ull && h == best) {
            ++p;
            float val = __uint_as_float((unsigned)(best >> 32));
            unsigned lin = 0xFFFFFFFFu - (unsigned)(best & 0xFFFFFFFFull);
            int q = (int)(lin / LL);
            int tok = (int)(lin - (unsigned)q * LL);
            int lo2 = 0, hi2 = 79, cls = 0;
            while (lo2 <= hi2) {
                int mid = (lo2 + hi2) >> 1;
                int tv = TOKEN_IDXS_C[mid];
                if (tv == tok) { cls = mid; break; }
                if (tv < tok) lo2 = mid + 1; else hi2 = mid - 1;
            }
            out[b * KSEL + j] = val;
            out[BATCH * KSEL + b * KSEL + j] = (float)cls;
            const float* bb = out_bbox + ((size_t)(b * QQ + q)) * 4;
            float cx = bb[0], cy = bb[1], w = bb[2], hh = bb[3];
            float img_h = target_sizes[b * 2 + 0];
            float img_w = target_sizes[b * 2 + 1];
            float* ob = out + 2 * BATCH * KSEL + ((size_t)(b * KSEL + j)) * 4;
            ob[0] = (cx - 0.5f * w) * img_w;
            ob[1] = (cy - 0.5f * hh) * img_h;
            ob[2] = (cx + 0.5f * w) * img_w;
            ob[3] = (cy + 0.5f * hh) * img_h;
        }
        __syncthreads();
    }
}

// ---------------- launch ----------------
extern "C" void kernel_launch(void* const* d_in, const int* in_sizes, int n_in,
                              void* d_out, int out_size) {
    const float* out_logits   = (const float*)d_in[0];
    const float* out_bbox     = (const float*)d_in[1];
    const float* pos_map      = (const float*)d_in[2];
    const float* target_sizes = (const float*)d_in[3];
    float* out = (float*)d_out;

    cudaFuncSetAttribute(k_gemm, cudaFuncAttributeMaxDynamicSharedMemorySize,
                         SMEM_TOTAL);

    k_convert<<<2048, NTHREADS>>>(out_logits, pos_map);
    k_threshold<<<BATCH, NTHREADS>>>(pos_map);
    dim3 grid(LLPAD / BN, MM / BM);   // 7 x 450, N fastest for A reuse in L2
    k_gemm<<<grid, NTHREADS, SMEM_TOTAL>>>();
    k_final<<<BATCH, NTHREADS>>>(out_bbox, target_sizes, out);
}

// round 4
// speedup vs baseline: 3.2360x; 1.7234x over previous
#include <cuda_runtime.h>
#include <cuda_fp16.h>
#include <math.h>
#include <stdint.h>

// ---------------- problem constants ----------------
#define BATCH 64
#define QQ 900
#define TT 256
#define LL 769
#define LLPAD 896            // 7 * 128
#define MM (BATCH * QQ)      // 57600
#define KSEL 50
#define CAP_G 16384          // global candidate cap per batch
#define NSAMP 1024
#define SAMP_STRIDE 675
#define RANK_SEL 4
#define MARGIN 0.02f
#define NTHREADS 256

// GEMM tiling
#define BM 128
#define BN 128
#define BK 64
#define PITCH 144            // bytes per 64-col fp16 row (conflict-free ldmatrix)
#define ST_A 18432           // 128 * 144
#define ST_STAGE 36864       // A + B
#define CAND_OFF 73728       // after 2 stages
#define CAND_CAP 4096        // per-region smem candidate cap
#define SMEM_TOTAL (CAND_OFF + 16 + 2 * CAND_CAP * 4)   // 106512

// ---------------- static scratch ----------------
__device__ __align__(256) float  g_sig[MM * TT];       // 59 MB fp32 sigmoid
__device__ __align__(256) __half g_Ah[MM * TT];        // 29.5 MB fp16
__device__ __align__(256) __half g_Bh[LLPAD * TT];     // fp16 pos_map (padded)
__device__ float              g_thr[BATCH];
__device__ int                g_cnt[BATCH * 32];       // 128B stride per batch
__device__ unsigned int       g_lin[BATCH * CAP_G];    // candidate linear idx
__device__ unsigned long long g_key[BATCH * CAP_G];    // refined keys

__constant__ int TOKEN_IDXS_C[80] = {
    0, 9, 19, 25, 38, 49, 55, 63, 71, 78, 94, 109, 121, 137, 145, 152, 158,
    164, 172, 180, 186, 197, 204, 212, 222, 233, 244, 254, 260, 271, 281, 288,
    300, 314, 321, 336, 353, 366, 378, 394, 403, 416, 422, 429, 437, 445, 452,
    461, 469, 480, 489, 500, 509, 519, 527, 535, 542, 550, 558, 573, 579, 594,
    603, 608, 617, 625, 634, 645, 658, 670, 677, 687, 694, 709, 716, 724, 731,
    742, 755, 768};

// ---------------- PTX helpers ----------------
__device__ __forceinline__ uint32_t smem_u32(const void* p) {
    uint32_t a;
    asm("{ .reg .u64 t; cvta.to.shared.u64 t, %1; cvt.u32.u64 %0, t; }"
        : "=r"(a) : "l"(p));
    return a;
}
__device__ __forceinline__ void cpa16(uint32_t s, const void* g) {
    asm volatile("cp.async.cg.shared.global [%0], [%1], 16;" :: "r"(s), "l"(g));
}
#define CP_COMMIT() asm volatile("cp.async.commit_group;" ::: "memory")
#define CP_WAIT1()  asm volatile("cp.async.wait_group 1;" ::: "memory")
#define CP_WAIT0()  asm volatile("cp.async.wait_group 0;" ::: "memory")

__device__ __forceinline__ void ldsm4(uint32_t& r0, uint32_t& r1, uint32_t& r2,
                                      uint32_t& r3, uint32_t addr) {
    asm volatile("ldmatrix.sync.aligned.m8n8.x4.shared.b16 {%0,%1,%2,%3}, [%4];"
                 : "=r"(r0), "=r"(r1), "=r"(r2), "=r"(r3) : "r"(addr));
}
__device__ __forceinline__ void mma16816(float* d, const uint32_t* a,
                                         uint32_t b0, uint32_t b1) {
    asm volatile(
        "mma.sync.aligned.m16n8k16.row.col.f32.f16.f16.f32 "
        "{%0,%1,%2,%3}, {%4,%5,%6,%7}, {%8,%9}, {%0,%1,%2,%3};"
        : "+f"(d[0]), "+f"(d[1]), "+f"(d[2]), "+f"(d[3])
        : "r"(a[0]), "r"(a[1]), "r"(a[2]), "r"(a[3]), "r"(b0), "r"(b1));
}

// ---------------- K1: sigmoid -> fp32 + fp16; pos_map -> fp16 ----------------
__global__ void k_convert(const float* __restrict__ logits,
                          const float* __restrict__ pos_map) {
    int stride = gridDim.x * blockDim.x;
    int tid0 = blockIdx.x * blockDim.x + threadIdx.x;

    int n4a = MM * TT / 4;
    const float4* in = (const float4*)logits;
    float4* sig4 = (float4*)g_sig;
    __half2* ah2 = (__half2*)g_Ah;
    for (int i = tid0; i < n4a; i += stride) {
        float4 v = in[i];
        float4 s;
        s.x = 1.f / (1.f + expf(-v.x));
        s.y = 1.f / (1.f + expf(-v.y));
        s.z = 1.f / (1.f + expf(-v.z));
        s.w = 1.f / (1.f + expf(-v.w));
        sig4[i] = s;
        ah2[i * 2]     = __floats2half2_rn(s.x, s.y);
        ah2[i * 2 + 1] = __floats2half2_rn(s.z, s.w);
    }

    int n4b = LLPAD * TT / 4;
    const float4* pin = (const float4*)pos_map;
    __half2* bh2 = (__half2*)g_Bh;
    for (int i = tid0; i < n4b; i += stride) {
        int l = i >> 6;
        float4 v;
        if (l < LL) v = pin[i];
        else        v = make_float4(0.f, 0.f, 0.f, 0.f);
        bh2[i * 2]     = __floats2half2_rn(v.x, v.y);
        bh2[i * 2 + 1] = __floats2half2_rn(v.z, v.w);
    }
}

// ---------------- K2: per-batch sampled threshold (exact fp32 dots) --------
__global__ void k_threshold(const float* __restrict__ pos_map) {
    int b = blockIdx.x;
    int tid = threadIdx.x;
    int warp = tid >> 5, lane = tid & 31;
    __shared__ float samp[NSAMP];
    __shared__ float red[NTHREADS];

    if (tid == 0) g_cnt[b * 32] = 0;

    for (int i = warp; i < NSAMP; i += 8) {
        int s = i * SAMP_STRIDE;
        int q = s / LL;
        int l = s - q * LL;
        const float4* A4 = (const float4*)(g_sig + (size_t)(b * QQ + q) * TT);
        const float4* B4 = (const float4*)(pos_map + (size_t)l * TT);
        float4 a0 = A4[lane], a1 = A4[lane + 32];
        float4 b0 = B4[lane], b1 = B4[lane + 32];
        float sum = a0.x * b0.x + a0.y * b0.y + a0.z * b0.z + a0.w * b0.w +
                    a1.x * b1.x + a1.y * b1.y + a1.z * b1.z + a1.w * b1.w;
        #pragma unroll
        for (int off = 16; off > 0; off >>= 1)
            sum += __shfl_down_sync(0xFFFFFFFFu, sum, off);
        if (lane == 0) samp[i] = sum;
    }
    __syncthreads();

    float prev = 3.4e38f;
    for (int it = 0; it < RANK_SEL; ++it) {
        float best = -3.4e38f;
        for (int i = tid; i < NSAMP; i += NTHREADS) {
            float v = samp[i];
            if (v < prev && v > best) best = v;
        }
        red[tid] = best;
        __syncthreads();
        for (int s = NTHREADS / 2; s > 0; s >>= 1) {
            if (tid < s && red[tid + s] > red[tid]) red[tid] = red[tid + s];
            __syncthreads();
        }
        prev = red[0];
        __syncthreads();
    }
    if (tid == 0) g_thr[b] = prev - MARGIN;
}

// ---------------- K3: single-pass fp16 HMMA GEMM + filter ----------------
__device__ __forceinline__ void load_stage(uint32_t sb, int s, int kc,
                                           int m0, int n0, int tid) {
    uint32_t base = sb + s * ST_STAGE;
    #pragma unroll
    for (int i = 0; i < 4; ++i) {
        int idx = tid + 256 * i;        // 0..1023
        int row = idx >> 3;             // 0..127
        int kv = idx & 7;               // 16B vec within 128B row
        uint32_t so = (uint32_t)(row * PITCH + kv * 16);
        size_t ga = (size_t)(m0 + row) * TT + kc * BK + kv * 8;
        size_t gb = (size_t)(n0 + row) * TT + kc * BK + kv * 8;
        cpa16(base + so,        g_Ah + ga);
        cpa16(base + ST_A + so, g_Bh + gb);
    }
    CP_COMMIT();
}

__global__ void __launch_bounds__(NTHREADS, 2) k_gemm() {
    extern __shared__ char smem[];
    uint32_t sb = smem_u32(smem);
    unsigned int* scnt = (unsigned int*)(smem + CAND_OFF);       // [0]=r0,[1]=r1
    unsigned int* sbase = scnt + 2;
    unsigned int* sent = scnt + 4;                               // entries

    int tid = threadIdx.x;
    int wid = tid >> 5, lane = tid & 31;
    int warp_m = wid >> 2;      // 0..1  (64 rows)
    int warp_n = wid & 3;       // 0..3  (32 cols)
    int m0 = blockIdx.y * BM;
    int n0 = blockIdx.x * BN;
    int b0 = m0 / QQ;
    int b1 = (m0 + BM - 1) / QQ;

    if (tid < 2) scnt[tid] = 0;

    float acc[4][4][4];
    #pragma unroll
    for (int a = 0; a < 4; ++a)
        #pragma unroll
        for (int b = 0; b < 4; ++b)
            #pragma unroll
            for (int c = 0; c < 4; ++c) acc[a][b][c] = 0.f;

    int a_row = (lane & 15);
    int a_cb  = (lane >> 4) * 16;
    int b_row = (lane & 7) + ((lane >> 4) & 1) * 8;
    int b_cb  = ((lane >> 3) & 1) * 16;

    load_stage(sb, 0, 0, m0, n0, tid);

    const int NKC = TT / BK;   // 4
    for (int kc = 0; kc < NKC; ++kc) {
        int s = kc & 1;
        if (kc + 1 < NKC) {
            load_stage(sb, (kc + 1) & 1, kc + 1, m0, n0, tid);
            CP_WAIT1();
        } else {
            CP_WAIT0();
        }
        __syncthreads();

        uint32_t Abase = sb + s * ST_STAGE +
                         (uint32_t)((warp_m * 64 + a_row) * PITCH) + a_cb;
        uint32_t Bbase = sb + s * ST_STAGE + ST_A +
                         (uint32_t)((warp_n * 32 + b_row) * PITCH) + b_cb;

        #pragma unroll
        for (int k16 = 0; k16 < 4; ++k16) {
            uint32_t koff = (uint32_t)(k16 * 32);
            uint32_t af[4][4], bf[2][4];
            #pragma unroll
            for (int mt = 0; mt < 4; ++mt)
                ldsm4(af[mt][0], af[mt][1], af[mt][2], af[mt][3],
                      Abase + (uint32_t)(mt * 16 * PITCH) + koff);
            #pragma unroll
            for (int nt = 0; nt < 2; ++nt)
                ldsm4(bf[nt][0], bf[nt][1], bf[nt][2], bf[nt][3],
                      Bbase + (uint32_t)(nt * 16 * PITCH) + koff);
            #pragma unroll
            for (int mt = 0; mt < 4; ++mt)
                #pragma unroll
                for (int nt16 = 0; nt16 < 2; ++nt16)
                    #pragma unroll
                    for (int h = 0; h < 2; ++h)
                        mma16816(acc[mt][nt16 * 2 + h], af[mt],
                                 bf[nt16][2 * h], bf[nt16][2 * h + 1]);
        }
        __syncthreads();
    }

    // ---------------- epilogue: filter into smem, bulk-publish ------------
    int g = lane >> 2, tg = lane & 3;
    #pragma unroll
    for (int mt = 0; mt < 4; ++mt) {
        #pragma unroll
        for (int half = 0; half < 2; ++half) {
            int m = m0 + warp_m * 64 + mt * 16 + g + half * 8;
            int b = m / QQ;
            int q = m - b * QQ;
            int r = (b == b0) ? 0 : 1;
            float thr = g_thr[b];
            #pragma unroll
            for (int nt = 0; nt < 4; ++nt) {
                #pragma unroll
                for (int j = 0; j < 2; ++j) {
                    float v = acc[mt][nt][half * 2 + j];
                    int l = n0 + warp_n * 32 + nt * 8 + tg * 2 + j;
                    if (l < LL && v >= thr) {
                        unsigned lin = (unsigned)(q * LL + l);
                        unsigned pos = atomicAdd(&scnt[r], 1u);
                        if (pos < CAND_CAP) {
                            sent[r * CAND_CAP + pos] = lin;
                        } else {  // overflow fallback (rare): direct global
                            int gp = atomicAdd(&g_cnt[b * 32], 1);
                            if (gp < CAP_G) g_lin[(size_t)b * CAP_G + gp] = lin;
                        }
                    }
                }
            }
        }
    }
    __syncthreads();
    if (tid < 2) {
        unsigned c = scnt[tid];
        if (c > CAND_CAP) c = CAND_CAP;
        scnt[tid] = c;
        int bb = tid == 0 ? b0 : b1;
        sbase[tid] = (c > 0) ? (unsigned)atomicAdd(&g_cnt[bb * 32], (int)c) : 0u;
    }
    __syncthreads();
    {
        unsigned c0 = scnt[0], base0 = sbase[0];
        for (unsigned i = tid; i < c0; i += NTHREADS) {
            unsigned dst = base0 + i;
            if (dst < CAP_G) g_lin[(size_t)b0 * CAP_G + dst] = sent[i];
        }
        unsigned c1 = scnt[1], base1 = sbase[1];
        for (unsigned i = tid; i < c1; i += NTHREADS) {
            unsigned dst = base1 + i;
            if (dst < CAP_G) g_lin[(size_t)b1 * CAP_G + dst] = sent[CAND_CAP + i];
        }
    }
}

// ---------------- K3b: exact fp32 refinement (warp per candidate) ---------
__global__ void k_refine(const float* __restrict__ pos_map) {
    int b = blockIdx.y;
    int tid = threadIdx.x;
    int wid = tid >> 5, lane = tid & 31;
    int n = g_cnt[b * 32];
    if (n > CAP_G) n = CAP_G;

    for (int i = blockIdx.x * 8 + wid; i < n; i += gridDim.x * 8) {
        unsigned lin = g_lin[(size_t)b * CAP_G + i];
        int q = (int)(lin / LL);
        int l = (int)(lin - (unsigned)q * LL);
        const float4* A4 = (const float4*)(g_sig + (size_t)(b * QQ + q) * TT);
        const float4* B4 = (const float4*)(pos_map + (size_t)l * TT);
        float4 a0 = A4[lane], a1 = A4[lane + 32];
        float4 p0 = B4[lane], p1 = B4[lane + 32];
        float sum = a0.x * p0.x + a0.y * p0.y + a0.z * p0.z + a0.w * p0.w +
                    a1.x * p1.x + a1.y * p1.y + a1.z * p1.z + a1.w * p1.w;
        #pragma unroll
        for (int off = 16; off > 0; off >>= 1)
            sum += __shfl_xor_sync(0xFFFFFFFFu, sum, off);
        if (lane == 0) {
            g_key[(size_t)b * CAP_G + i] =
                ((unsigned long long)__float_as_uint(sum) << 32) |
                (unsigned long long)(0xFFFFFFFFu - lin);
        }
    }
}

// ---------------- K4: per-batch top-50 + outputs ----------------
__global__ void k_final(const float* __restrict__ out_bbox,
                        const float* __restrict__ target_sizes,
                        float* __restrict__ out) {
    int b = blockIdx.x;
    int tid = threadIdx.x;
    int wid = tid >> 5, lane = tid & 31;
    __shared__ unsigned long long wmax[8];

    int n = g_cnt[b * 32];
    if (n > CAP_G) n = CAP_G;
    const unsigned long long* keys = g_key + (size_t)b * CAP_G;

    unsigned long long prev = 0xFFFFFFFFFFFFFFFFull;
    for (int j = 0; j < KSEL; ++j) {
        unsigned long long best = 0ull;
        for (int t = tid; t < n; t += NTHREADS) {
            unsigned long long k = keys[t];
            if (k < prev && k > best) best = k;
        }
        #pragma unroll
        for (int off = 16; off > 0; off >>= 1) {
            unsigned long long o = __shfl_xor_sync(0xFFFFFFFFu, best, off);
            if (o > best) best = o;
        }
        if (lane == 0) wmax[wid] = best;
        __syncthreads();
        if (tid == 0) {
            unsigned long long m = wmax[0];
            #pragma unroll
            for (int w = 1; w < 8; ++w) if (wmax[w] > m) m = wmax[w];
            wmax[0] = m;
        }
        __syncthreads();
        unsigned long long key = wmax[0];
        prev = key;

        if (tid == 0) {
            float val = __uint_as_float((unsigned)(key >> 32));
            unsigned lin = 0xFFFFFFFFu - (unsigned)(key & 0xFFFFFFFFull);
            int q = (int)(lin / LL);
            int tok = (int)(lin - (unsigned)q * LL);
            int lo2 = 0, hi2 = 79, cls = 0;
            while (lo2 <= hi2) {
                int mid = (lo2 + hi2) >> 1;
                int tv = TOKEN_IDXS_C[mid];
                if (tv == tok) { cls = mid; break; }
                if (tv < tok) lo2 = mid + 1; else hi2 = mid - 1;
            }
            out[b * KSEL + j] = val;
            out[BATCH * KSEL + b * KSEL + j] = (float)cls;
            const float* bb = out_bbox + ((size_t)(b * QQ + q)) * 4;
            float cx = bb[0], cy = bb[1], w = bb[2], hh = bb[3];
            float img_h = target_sizes[b * 2 + 0];
            float img_w = target_sizes[b * 2 + 1];
            float* ob = out + 2 * BATCH * KSEL + ((size_t)(b * KSEL + j)) * 4;
            ob[0] = (cx - 0.5f * w) * img_w;
            ob[1] = (cy - 0.5f * hh) * img_h;
            ob[2] = (cx + 0.5f * w) * img_w;
            ob[3] = (cy + 0.5f * hh) * img_h;
        }
        __syncthreads();
    }
}

// ---------------- launch ----------------
extern "C" void kernel_launch(void* const* d_in, const int* in_sizes, int n_in,
                              void* d_out, int out_size) {
    const float* out_logits   = (const float*)d_in[0];
    const float* out_bbox     = (const float*)d_in[1];
    const float* pos_map      = (const float*)d_in[2];
    const float* target_sizes = (const float*)d_in[3];
    float* out = (float*)d_out;

    cudaFuncSetAttribute(k_gemm, cudaFuncAttributeMaxDynamicSharedMemorySize,
                         SMEM_TOTAL);

    k_convert<<<2048, NTHREADS>>>(out_logits, pos_map);
    k_threshold<<<BATCH, NTHREADS>>>(pos_map);
    dim3 grid(LLPAD / BN, MM / BM);   // 7 x 450
    k_gemm<<<grid, NTHREADS, SMEM_TOTAL>>>();
    k_refine<<<dim3(16, BATCH), NTHREADS>>>(pos_map);
    k_final<<<BATCH, NTHREADS>>>(out_bbox, target_sizes, out);
}

// round 5
// speedup vs baseline: 3.6181x; 1.1181x over previous
#include <cuda_runtime.h>
#include <cuda_fp16.h>
#include <math.h>
#include <stdint.h>

// ---------------- problem constants ----------------
#define BATCH 64
#define QQ 900
#define TT 256
#define LL 769
#define LLPAD 896            // 7 * 128
#define MM (BATCH * QQ)      // 57600
#define KSEL 50
#define CAP_G 16384
#define NSAMP 1024
#define SAMP_STRIDE 675
#define RANK_SEL 4
#define MARGIN 0.08f         // covers int8 quantization noise (sigma ~0.015)
#define NTHREADS 256
#define INV_SCALE (1.0f / 65025.0f)   // 1/(255*255)

// GEMM tiling (int8)
#define BM 128
#define BN 128
#define BK 128               // k-bytes per stage
#define PITCH 144            // bytes per 128-byte row (conflict-free ldmatrix)
#define ST_A 18432           // 128 * 144
#define ST_STAGE 36864       // A + B
#define CAND_OFF 73728
#define CAND_CAP 4096
#define SMEM_TOTAL (CAND_OFF + 16 + 2 * CAND_CAP * 4)   // 106512

// ---------------- static scratch ----------------
__device__ __align__(256) float         g_sig[MM * TT];      // 59 MB fp32 sigmoid
__device__ __align__(256) unsigned char g_Aq[MM * TT];       // 14.7 MB u8
__device__ __align__(256) unsigned char g_Bq[LLPAD * TT];    // u8 pos_map (padded)
__device__ float              g_thr[BATCH];
__device__ int                g_cnt[BATCH * 32];             // 128B stride per batch
__device__ unsigned int       g_lin[BATCH * CAP_G];
__device__ unsigned long long g_key[BATCH * CAP_G];

__constant__ int TOKEN_IDXS_C[80] = {
    0, 9, 19, 25, 38, 49, 55, 63, 71, 78, 94, 109, 121, 137, 145, 152, 158,
    164, 172, 180, 186, 197, 204, 212, 222, 233, 244, 254, 260, 271, 281, 288,
    300, 314, 321, 336, 353, 366, 378, 394, 403, 416, 422, 429, 437, 445, 452,
    461, 469, 480, 489, 500, 509, 519, 527, 535, 542, 550, 558, 573, 579, 594,
    603, 608, 617, 625, 634, 645, 658, 670, 677, 687, 694, 709, 716, 724, 731,
    742, 755, 768};

// ---------------- PTX helpers ----------------
__device__ __forceinline__ uint32_t smem_u32(const void* p) {
    uint32_t a;
    asm("{ .reg .u64 t; cvta.to.shared.u64 t, %1; cvt.u32.u64 %0, t; }"
        : "=r"(a) : "l"(p));
    return a;
}
__device__ __forceinline__ void cpa16(uint32_t s, const void* g) {
    asm volatile("cp.async.cg.shared.global [%0], [%1], 16;" :: "r"(s), "l"(g));
}
#define CP_COMMIT() asm volatile("cp.async.commit_group;" ::: "memory")
#define CP_WAIT1()  asm volatile("cp.async.wait_group 1;" ::: "memory")
#define CP_WAIT0()  asm volatile("cp.async.wait_group 0;" ::: "memory")

__device__ __forceinline__ void ldsm4(uint32_t& r0, uint32_t& r1, uint32_t& r2,
                                      uint32_t& r3, uint32_t addr) {
    asm volatile("ldmatrix.sync.aligned.m8n8.x4.shared.b16 {%0,%1,%2,%3}, [%4];"
                 : "=r"(r0), "=r"(r1), "=r"(r2), "=r"(r3) : "r"(addr));
}
__device__ __forceinline__ void imma16832(int* d, const uint32_t* a,
                                          uint32_t b0, uint32_t b1) {
    asm volatile(
        "mma.sync.aligned.m16n8k32.row.col.s32.u8.u8.s32 "
        "{%0,%1,%2,%3}, {%4,%5,%6,%7}, {%8,%9}, {%0,%1,%2,%3};"
        : "+r"(d[0]), "+r"(d[1]), "+r"(d[2]), "+r"(d[3])
        : "r"(a[0]), "r"(a[1]), "r"(a[2]), "r"(a[3]), "r"(b0), "r"(b1));
}

// ---------------- K1: sigmoid -> fp32 + u8; pos_map -> u8 ----------------
__global__ void k_convert(const float* __restrict__ logits,
                          const float* __restrict__ pos_map) {
    int stride = gridDim.x * blockDim.x;
    int tid0 = blockIdx.x * blockDim.x + threadIdx.x;

    int n4a = MM * TT / 4;
    const float4* in = (const float4*)logits;
    float4* sig4 = (float4*)g_sig;
    unsigned int* aq4 = (unsigned int*)g_Aq;
    for (int i = tid0; i < n4a; i += stride) {
        float4 v = in[i];
        float4 s;
        s.x = 1.f / (1.f + expf(-v.x));
        s.y = 1.f / (1.f + expf(-v.y));
        s.z = 1.f / (1.f + expf(-v.z));
        s.w = 1.f / (1.f + expf(-v.w));
        sig4[i] = s;
        unsigned q0 = __float2uint_rn(s.x * 255.f);
        unsigned q1 = __float2uint_rn(s.y * 255.f);
        unsigned q2 = __float2uint_rn(s.z * 255.f);
        unsigned q3 = __float2uint_rn(s.w * 255.f);
        aq4[i] = q0 | (q1 << 8) | (q2 << 16) | (q3 << 24);
    }

    int n4b = LLPAD * TT / 4;
    const float4* pin = (const float4*)pos_map;
    unsigned int* bq4 = (unsigned int*)g_Bq;
    for (int i = tid0; i < n4b; i += stride) {
        int l = i >> 6;
        unsigned pack = 0;
        if (l < LL) {
            float4 v = pin[i];
            unsigned q0 = __float2uint_rn(v.x * 255.f);
            unsigned q1 = __float2uint_rn(v.y * 255.f);
            unsigned q2 = __float2uint_rn(v.z * 255.f);
            unsigned q3 = __float2uint_rn(v.w * 255.f);
            pack = q0 | (q1 << 8) | (q2 << 16) | (q3 << 24);
        }
        bq4[i] = pack;
    }
}

// ---------------- K2: per-batch sampled threshold (exact fp32 dots) --------
__global__ void k_threshold(const float* __restrict__ pos_map) {
    int b = blockIdx.x;
    int tid = threadIdx.x;
    int warp = tid >> 5, lane = tid & 31;
    __shared__ float samp[NSAMP];
    __shared__ float red[NTHREADS];

    if (tid == 0) g_cnt[b * 32] = 0;

    for (int i = warp; i < NSAMP; i += 8) {
        int s = i * SAMP_STRIDE;
        int q = s / LL;
        int l = s - q * LL;
        const float4* A4 = (const float4*)(g_sig + (size_t)(b * QQ + q) * TT);
        const float4* B4 = (const float4*)(pos_map + (size_t)l * TT);
        float4 a0 = A4[lane], a1 = A4[lane + 32];
        float4 b0 = B4[lane], b1 = B4[lane + 32];
        float sum = a0.x * b0.x + a0.y * b0.y + a0.z * b0.z + a0.w * b0.w +
                    a1.x * b1.x + a1.y * b1.y + a1.z * b1.z + a1.w * b1.w;
        #pragma unroll
        for (int off = 16; off > 0; off >>= 1)
            sum += __shfl_down_sync(0xFFFFFFFFu, sum, off);
        if (lane == 0) samp[i] = sum;
    }
    __syncthreads();

    float prev = 3.4e38f;
    for (int it = 0; it < RANK_SEL; ++it) {
        float best = -3.4e38f;
        for (int i = tid; i < NSAMP; i += NTHREADS) {
            float v = samp[i];
            if (v < prev && v > best) best = v;
        }
        red[tid] = best;
        __syncthreads();
        for (int s = NTHREADS / 2; s > 0; s >>= 1) {
            if (tid < s && red[tid + s] > red[tid]) red[tid] = red[tid + s];
            __syncthreads();
        }
        prev = red[0];
        __syncthreads();
    }
    if (tid == 0) g_thr[b] = prev - MARGIN;
}

// ---------------- K3: int8 IMMA GEMM + filter ----------------
__device__ __forceinline__ void load_stage(uint32_t sb, int s, int kc,
                                           int m0, int n0, int tid) {
    uint32_t base = sb + s * ST_STAGE;
    #pragma unroll
    for (int i = 0; i < 4; ++i) {
        int idx = tid + 256 * i;        // 0..1023
        int row = idx >> 3;             // 0..127
        int kv = idx & 7;               // 16B vec within 128B row
        uint32_t so = (uint32_t)(row * PITCH + kv * 16);
        size_t ga = (size_t)(m0 + row) * TT + kc * BK + kv * 16;
        size_t gb = (size_t)(n0 + row) * TT + kc * BK + kv * 16;
        cpa16(base + so,        g_Aq + ga);
        cpa16(base + ST_A + so, g_Bq + gb);
    }
    CP_COMMIT();
}

__global__ void __launch_bounds__(NTHREADS, 2) k_gemm() {
    extern __shared__ char smem[];
    uint32_t sb = smem_u32(smem);
    unsigned int* scnt = (unsigned int*)(smem + CAND_OFF);
    unsigned int* sbase = scnt + 2;
    unsigned int* sent = scnt + 4;

    int tid = threadIdx.x;
    int wid = tid >> 5, lane = tid & 31;
    int warp_m = wid >> 2;      // 0..1  (64 rows)
    int warp_n = wid & 3;       // 0..3  (32 cols)
    int m0 = blockIdx.y * BM;
    int n0 = blockIdx.x * BN;
    int b0 = m0 / QQ;
    int b1 = (m0 + BM - 1) / QQ;

    if (tid < 2) scnt[tid] = 0;

    int acc[4][4][4];
    #pragma unroll
    for (int a = 0; a < 4; ++a)
        #pragma unroll
        for (int b = 0; b < 4; ++b)
            #pragma unroll
            for (int c = 0; c < 4; ++c) acc[a][b][c] = 0;

    int a_row = (lane & 15);
    int a_cb  = (lane >> 4) * 16;
    int b_row = (lane & 7) + ((lane >> 4) & 1) * 8;
    int b_cb  = ((lane >> 3) & 1) * 16;

    load_stage(sb, 0, 0, m0, n0, tid);

    const int NKC = TT / BK;   // 2
    for (int kc = 0; kc < NKC; ++kc) {
        int s = kc & 1;
        if (kc + 1 < NKC) {
            load_stage(sb, (kc + 1) & 1, kc + 1, m0, n0, tid);
            CP_WAIT1();
        } else {
            CP_WAIT0();
        }
        __syncthreads();

        uint32_t Abase = sb + s * ST_STAGE +
                         (uint32_t)((warp_m * 64 + a_row) * PITCH) + a_cb;
        uint32_t Bbase = sb + s * ST_STAGE + ST_A +
                         (uint32_t)((warp_n * 32 + b_row) * PITCH) + b_cb;

        #pragma unroll
        for (int k32 = 0; k32 < 4; ++k32) {
            uint32_t koff = (uint32_t)(k32 * 32);
            uint32_t af[4][4], bf[2][4];
            #pragma unroll
            for (int mt = 0; mt < 4; ++mt)
                ldsm4(af[mt][0], af[mt][1], af[mt][2], af[mt][3],
                      Abase + (uint32_t)(mt * 16 * PITCH) + koff);
            #pragma unroll
            for (int nt = 0; nt < 2; ++nt)
                ldsm4(bf[nt][0], bf[nt][1], bf[nt][2], bf[nt][3],
                      Bbase + (uint32_t)(nt * 16 * PITCH) + koff);
            #pragma unroll
            for (int mt = 0; mt < 4; ++mt)
                #pragma unroll
                for (int nt16 = 0; nt16 < 2; ++nt16)
                    #pragma unroll
                    for (int h = 0; h < 2; ++h)
                        imma16832(acc[mt][nt16 * 2 + h], af[mt],
                                  bf[nt16][2 * h], bf[nt16][2 * h + 1]);
        }
        __syncthreads();
    }

    // ---------------- epilogue: filter into smem, bulk-publish ------------
    int g = lane >> 2, tg = lane & 3;
    #pragma unroll
    for (int mt = 0; mt < 4; ++mt) {
        #pragma unroll
        for (int half = 0; half < 2; ++half) {
            int m = m0 + warp_m * 64 + mt * 16 + g + half * 8;
            int b = m / QQ;
            int q = m - b * QQ;
            int r = (b == b0) ? 0 : 1;
            float thr = g_thr[b];
            #pragma unroll
            for (int nt = 0; nt < 4; ++nt) {
                #pragma unroll
                for (int j = 0; j < 2; ++j) {
                    float v = (float)acc[mt][nt][half * 2 + j] * INV_SCALE;
                    int l = n0 + warp_n * 32 + nt * 8 + tg * 2 + j;
                    if (l < LL && v >= thr) {
                        unsigned lin = (unsigned)(q * LL + l);
                        unsigned pos = atomicAdd(&scnt[r], 1u);
                        if (pos < CAND_CAP) {
                            sent[r * CAND_CAP + pos] = lin;
                        } else {
                            int gp = atomicAdd(&g_cnt[b * 32], 1);
                            if (gp < CAP_G) g_lin[(size_t)b * CAP_G + gp] = lin;
                        }
                    }
                }
            }
        }
    }
    __syncthreads();
    if (tid < 2) {
        unsigned c = scnt[tid];
        if (c > CAND_CAP) c = CAND_CAP;
        scnt[tid] = c;
        int bb = tid == 0 ? b0 : b1;
        sbase[tid] = (c > 0) ? (unsigned)atomicAdd(&g_cnt[bb * 32], (int)c) : 0u;
    }
    __syncthreads();
    {
        unsigned c0 = scnt[0], base0 = sbase[0];
        for (unsigned i = tid; i < c0; i += NTHREADS) {
            unsigned dst = base0 + i;
            if (dst < CAP_G) g_lin[(size_t)b0 * CAP_G + dst] = sent[i];
        }
        unsigned c1 = scnt[1], base1 = sbase[1];
        for (unsigned i = tid; i < c1; i += NTHREADS) {
            unsigned dst = base1 + i;
            if (dst < CAP_G) g_lin[(size_t)b1 * CAP_G + dst] = sent[CAND_CAP + i];
        }
    }
}

// ---------------- K3b: exact fp32 refinement (warp per candidate, ILP2) ----
__global__ void k_refine(const float* __restrict__ pos_map) {
    int b = blockIdx.y;
    int tid = threadIdx.x;
    int wid = tid >> 5, lane = tid & 31;
    int n = g_cnt[b * 32];
    if (n > CAP_G) n = CAP_G;
    int nwarp = gridDim.x * 8;

    for (int i0 = (blockIdx.x * 8 + wid) * 2; i0 < n; i0 += nwarp * 2) {
        int i1 = i0 + 1;
        bool has1 = i1 < n;
        unsigned lin0 = g_lin[(size_t)b * CAP_G + i0];
        unsigned lin1 = has1 ? g_lin[(size_t)b * CAP_G + i1] : lin0;
        int q0 = (int)(lin0 / LL), l0 = (int)(lin0 - (unsigned)q0 * LL);
        int q1 = (int)(lin1 / LL), l1 = (int)(lin1 - (unsigned)q1 * LL);
        const float4* A0 = (const float4*)(g_sig + (size_t)(b * QQ + q0) * TT);
        const float4* B0 = (const float4*)(pos_map + (size_t)l0 * TT);
        const float4* A1 = (const float4*)(g_sig + (size_t)(b * QQ + q1) * TT);
        const float4* B1 = (const float4*)(pos_map + (size_t)l1 * TT);
        float4 a00 = A0[lane], a01 = A0[lane + 32];
        float4 p00 = B0[lane], p01 = B0[lane + 32];
        float4 a10 = A1[lane], a11 = A1[lane + 32];
        float4 p10 = B1[lane], p11 = B1[lane + 32];
        float s0 = a00.x * p00.x + a00.y * p00.y + a00.z * p00.z + a00.w * p00.w +
                   a01.x * p01.x + a01.y * p01.y + a01.z * p01.z + a01.w * p01.w;
        float s1 = a10.x * p10.x + a10.y * p10.y + a10.z * p10.z + a10.w * p10.w +
                   a11.x * p11.x + a11.y * p11.y + a11.z * p11.z + a11.w * p11.w;
        #pragma unroll
        for (int off = 16; off > 0; off >>= 1) {
            s0 += __shfl_xor_sync(0xFFFFFFFFu, s0, off);
            s1 += __shfl_xor_sync(0xFFFFFFFFu, s1, off);
        }
        if (lane == 0) {
            g_key[(size_t)b * CAP_G + i0] =
                ((unsigned long long)__float_as_uint(s0) << 32) |
                (unsigned long long)(0xFFFFFFFFu - lin0);
            if (has1)
                g_key[(size_t)b * CAP_G + i1] =
                    ((unsigned long long)__float_as_uint(s1) << 32) |
                    (unsigned long long)(0xFFFFFFFFu - lin1);
        }
    }
}

// ---------------- K4: per-batch top-50 + outputs ----------------
__global__ void k_final(const float* __restrict__ out_bbox,
                        const float* __restrict__ target_sizes,
                        float* __restrict__ out) {
    int b = blockIdx.x;
    int tid = threadIdx.x;
    int wid = tid >> 5, lane = tid & 31;
    __shared__ unsigned long long wmax[8];

    int n = g_cnt[b * 32];
    if (n > CAP_G) n = CAP_G;
    const unsigned long long* keys = g_key + (size_t)b * CAP_G;

    unsigned long long prev = 0xFFFFFFFFFFFFFFFFull;
    for (int j = 0; j < KSEL; ++j) {
        unsigned long long best = 0ull;
        for (int t = tid; t < n; t += NTHREADS) {
            unsigned long long k = keys[t];
            if (k < prev && k > best) best = k;
        }
        #pragma unroll
        for (int off = 16; off > 0; off >>= 1) {
            unsigned long long o = __shfl_xor_sync(0xFFFFFFFFu, best, off);
            if (o > best) best = o;
        }
        if (lane == 0) wmax[wid] = best;
        __syncthreads();
        if (tid == 0) {
            unsigned long long m = wmax[0];
            #pragma unroll
            for (int w = 1; w < 8; ++w) if (wmax[w] > m) m = wmax[w];
            wmax[0] = m;
        }
        __syncthreads();
        unsigned long long key = wmax[0];
        prev = key;

        if (tid == 0) {
            float val = __uint_as_float((unsigned)(key >> 32));
            unsigned lin = 0xFFFFFFFFu - (unsigned)(key & 0xFFFFFFFFull);
            int q = (int)(lin / LL);
            int tok = (int)(lin - (unsigned)q * LL);
            int lo2 = 0, hi2 = 79, cls = 0;
            while (lo2 <= hi2) {
                int mid = (lo2 + hi2) >> 1;
                int tv = TOKEN_IDXS_C[mid];
                if (tv == tok) { cls = mid; break; }
                if (tv < tok) lo2 = mid + 1; else hi2 = mid - 1;
            }
            out[b * KSEL + j] = val;
            out[BATCH * KSEL + b * KSEL + j] = (float)cls;
            const float* bb = out_bbox + ((size_t)(b * QQ + q)) * 4;
            float cx = bb[0], cy = bb[1], w = bb[2], hh = bb[3];
            float img_h = target_sizes[b * 2 + 0];
            float img_w = target_sizes[b * 2 + 1];
            float* ob = out + 2 * BATCH * KSEL + ((size_t)(b * KSEL + j)) * 4;
            ob[0] = (cx - 0.5f * w) * img_w;
            ob[1] = (cy - 0.5f * hh) * img_h;
            ob[2] = (cx + 0.5f * w) * img_w;
            ob[3] = (cy + 0.5f * hh) * img_h;
        }
        __syncthreads();
    }
}

// ---------------- launch ----------------
extern "C" void kernel_launch(void* const* d_in, const int* in_sizes, int n_in,
                              void* d_out, int out_size) {
    const float* out_logits   = (const float*)d_in[0];
    const float* out_bbox     = (const float*)d_in[1];
    const float* pos_map      = (const float*)d_in[2];
    const float* target_sizes = (const float*)d_in[3];
    float* out = (float*)d_out;

    cudaFuncSetAttribute(k_gemm, cudaFuncAttributeMaxDynamicSharedMemorySize,
                         SMEM_TOTAL);

    k_convert<<<2048, NTHREADS>>>(out_logits, pos_map);
    k_threshold<<<BATCH, NTHREADS>>>(pos_map);
    dim3 grid(LLPAD / BN, MM / BM);   // 7 x 450
    k_gemm<<<grid, NTHREADS, SMEM_TOTAL>>>();
    k_refine<<<dim3(16, BATCH), NTHREADS>>>(pos_map);
    k_final<<<BATCH, NTHREADS>>>(out_bbox, target_sizes, out);
}